// round 7
// baseline (speedup 1.0000x reference)
#include <cuda_runtime.h>
#include <math.h>

#define B 64
#define T 512
#define E 256
#define U 256
#define Z 1024      /* 4*U */
#define HALFB 32    /* batches 0..31 -> SM branch; 32..63 -> CE memset branch */

__device__ __forceinline__ float sigm(float v) { return 1.0f / (1.0f + expf(-v)); }

// ---------------------------------------------------------------------------
// Shared rare-path device routine: replay the masked LSTM for batch b from
// t=0, writing out[b, t, :] for t in [t_lo, t_hi) and (optionally) final h.
// Keras masked semantics: state updates ONLY where token == 0 (mask True).
// Caller guarantees the batch HAS at least one active step.
// ---------------------------------------------------------------------------
__device__ void replay_lstm(int b, int t_lo, int t_hi, bool write_final,
                            const int*   __restrict__ x,
                            const float* __restrict__ emb,
                            const float* __restrict__ k0,
                            const float* __restrict__ r0,
                            const float* __restrict__ b0,
                            const float* __restrict__ k1,
                            const float* __restrict__ r1,
                            const float* __restrict__ b1,
                            float*       __restrict__ out)
{
    __shared__ int   acts[T];
    __shared__ float h0s[U];
    __shared__ float h1s[U];
    __shared__ float zbuf[Z];
    __shared__ float embs[E];

    const int j = threadIdx.x;

    for (int t = j; t < t_hi; t += 256)
        acts[t] = (x[(size_t)b * T + t] == 0);

    embs[j] = emb[j];                          // embedding row of token 0
    h0s[j]  = 0.0f;
    h1s[j]  = 0.0f;
    __syncthreads();

    // Constant layer-0 x-contribution: xz = emb[0,:] @ k0 + b0.
    float4 xz = reinterpret_cast<const float4*>(b0)[j];
    for (int e = 0; e < E; e++) {
        const float  ev = embs[e];
        const float4 kv = reinterpret_cast<const float4*>(k0 + (size_t)e * Z)[j];
        xz.x += ev * kv.x; xz.y += ev * kv.y; xz.z += ev * kv.z; xz.w += ev * kv.w;
    }
    const float4 b1v = reinterpret_cast<const float4*>(b1)[j];

    float c0 = 0.0f, c1 = 0.0f;

    for (int t = 0; t < t_hi; t++) {
        if (acts[t]) {
            // ---- layer 0: z = xz + h0 @ r0 ----
            float4 z = xz;
            #pragma unroll 4
            for (int k = 0; k < U; k++) {
                const float  hv = h0s[k];
                const float4 rv = reinterpret_cast<const float4*>(r0 + (size_t)k * Z)[j];
                z.x += hv * rv.x; z.y += hv * rv.y; z.z += hv * rv.z; z.w += hv * rv.w;
            }
            reinterpret_cast<float4*>(zbuf)[j] = z;
            __syncthreads();
            {
                const float ig = sigm (zbuf[0 * U + j]);
                const float fg = sigm (zbuf[1 * U + j]);
                const float gg = tanhf(zbuf[2 * U + j]);
                const float og = sigm (zbuf[3 * U + j]);
                c0 = fg * c0 + ig * gg;
                __syncthreads();               // matvec reads of h0s fully done
                h0s[j] = og * tanhf(c0);
            }
            __syncthreads();

            // ---- layer 1: w = b1 + h0 @ k1 + h1 @ r1 ----
            float4 w = b1v;
            #pragma unroll 2
            for (int k = 0; k < U; k++) {
                const float  h0v = h0s[k];
                const float  h1v = h1s[k];
                const float4 kv = reinterpret_cast<const float4*>(k1 + (size_t)k * Z)[j];
                const float4 rv = reinterpret_cast<const float4*>(r1 + (size_t)k * Z)[j];
                w.x += h0v * kv.x + h1v * rv.x;
                w.y += h0v * kv.y + h1v * rv.y;
                w.z += h0v * kv.z + h1v * rv.z;
                w.w += h0v * kv.w + h1v * rv.w;
            }
            __syncthreads();                   // prior zbuf reads done
            reinterpret_cast<float4*>(zbuf)[j] = w;
            __syncthreads();
            {
                const float ig = sigm (zbuf[0 * U + j]);
                const float fg = sigm (zbuf[1 * U + j]);
                const float gg = tanhf(zbuf[2 * U + j]);
                const float og = sigm (zbuf[3 * U + j]);
                c1 = fg * c1 + ig * gg;
                __syncthreads();               // matvec reads of h1s fully done
                h1s[j] = og * tanhf(c1);
            }
            __syncthreads();
        }
        if (t >= t_lo)
            out[(size_t)b * T * U + (size_t)t * U + j] = h1s[j];
    }
    if (write_final)
        out[(size_t)B * T * U + (size_t)b * U + j] = h1s[j];
}

// ---------------------------------------------------------------------------
// Branch A (SM path): batches 0..31. 64 CTAs = (batch, 256-step chunk).
// Common case: stream 256KB of zero STG.128 per CTA. Rare: inline replay.
// ---------------------------------------------------------------------------
__global__ __launch_bounds__(256)
void store_low_kernel(const int*   __restrict__ x,
                      const float* __restrict__ emb,
                      const float* __restrict__ k0,
                      const float* __restrict__ r0,
                      const float* __restrict__ b0,
                      const float* __restrict__ k1,
                      const float* __restrict__ r1,
                      const float* __restrict__ b1,
                      float*       __restrict__ out)
{
    const int b     = blockIdx.x >> 1;          // 0..31
    const int chunk = blockIdx.x & 1;
    const int t0    = chunk * 256;
    const int t_end = t0 + 256;
    const int j     = threadIdx.x;

    int pred = 0;
    if (j < t_end / 4) {
        const int4 v = reinterpret_cast<const int4*>(x + (size_t)b * T)[j];
        pred = (v.x == 0) | (v.y == 0) | (v.z == 0) | (v.w == 0);
    }
    const int any = __syncthreads_or(pred);

    if (!any) {
        const float4 zv = make_float4(0.f, 0.f, 0.f, 0.f);
        float4* dst = reinterpret_cast<float4*>(out + (size_t)b * T * U + (size_t)t0 * U);
        #pragma unroll
        for (int i = 0; i < 64; i++)            // 256*256 floats = 16384 f4 / 256 thr
            dst[i * 256 + j] = zv;
        if (chunk == 1 && j < U / 4) {
            float4* hdst = reinterpret_cast<float4*>(out + (size_t)B * T * U + (size_t)b * U);
            hdst[j] = zv;
        }
        return;
    }
    replay_lstm(b, t0, t_end, chunk == 1, x, emb, k0, r0, b0, k1, r1, b1, out);
}

// ---------------------------------------------------------------------------
// Branch B fixer (side stream, AFTER the memset of batches 32..63):
// common case = token scan + exit; rare = replay + overwrite.
// ---------------------------------------------------------------------------
__global__ __launch_bounds__(256)
void fix_high_kernel(const int*   __restrict__ x,
                     const float* __restrict__ emb,
                     const float* __restrict__ k0,
                     const float* __restrict__ r0,
                     const float* __restrict__ b0,
                     const float* __restrict__ k1,
                     const float* __restrict__ r1,
                     const float* __restrict__ b1,
                     float*       __restrict__ out)
{
    const int b = HALFB + blockIdx.x;           // 32..63
    const int j = threadIdx.x;

    int pred = 0;
    if (j < T / 4) {
        const int4 v = reinterpret_cast<const int4*>(x + (size_t)b * T)[j];
        pred = (v.x == 0) | (v.y == 0) | (v.z == 0) | (v.w == 0);
    }
    const int any = __syncthreads_or(pred);
    if (!any) return;                           // memset already produced zeros

    replay_lstm(b, 0, T, true, x, emb, k0, r0, b0, k1, r1, b1, out);
}

extern "C" void kernel_launch(void* const* d_in, const int* in_sizes, int n_in,
                              void* d_out, int out_size)
{
    const int*   x   = (const int*)  d_in[0];
    const float* emb = (const float*)d_in[1];
    const float* k0  = (const float*)d_in[2];
    const float* r0  = (const float*)d_in[3];
    const float* b0  = (const float*)d_in[4];
    const float* k1  = (const float*)d_in[5];
    const float* r1  = (const float*)d_in[6];
    const float* b1  = (const float*)d_in[7];
    float* out = (float*)d_out;

    // Lazily-created side stream + events (first call = correctness run, before
    // capture). Host-side objects only — no device memory.
    static cudaStream_t side = []{ cudaStream_t s;
        cudaStreamCreateWithFlags(&s, cudaStreamNonBlocking); return s; }();
    static cudaEvent_t ev_fork = []{ cudaEvent_t e;
        cudaEventCreateWithFlags(&e, cudaEventDisableTiming); return e; }();
    static cudaEvent_t ev_join = []{ cudaEvent_t e;
        cudaEventCreateWithFlags(&e, cudaEventDisableTiming); return e; }();

    // Fork: side stream joins the capture.
    cudaEventRecord(ev_fork, 0);
    cudaStreamWaitEvent(side, ev_fork, 0);

    // Branch B (copy engine + fixer) on side: batches 32..63.
    // main region of b in [32,64): 16,777,216 bytes; final-h tail: 32,768 bytes.
    cudaMemsetAsync(out + (size_t)HALFB * T * U, 0,
                    (size_t)HALFB * T * U * sizeof(float), side);
    cudaMemsetAsync(out + (size_t)B * T * U + (size_t)HALFB * U, 0,
                    (size_t)HALFB * U * sizeof(float), side);
    fix_high_kernel<<<B - HALFB, 256, 0, side>>>(x, emb, k0, r0, b0, k1, r1, b1, out);

    // Branch A (SM stores) on the captured stream, concurrent with branch B.
    store_low_kernel<<<HALFB * 2, 256>>>(x, emb, k0, r0, b0, k1, r1, b1, out);

    // Join.
    cudaEventRecord(ev_join, side);
    cudaStreamWaitEvent(0, ev_join, 0);
}

// round 8
// speedup vs baseline: 3.0627x; 3.0627x over previous
#include <cuda_runtime.h>
#include <math.h>

#define B 64
#define T 512
#define E 256
#define U 256
#define Z 1024      /* 4*U */
#define CHUNK 64
#define NCHUNK (T / CHUNK)   /* 8 */

__device__ __forceinline__ float sigm(float v) { return 1.0f / (1.0f + expf(-v)); }

// Single-node design (measured floor: 33.5MB mandatory writes / ~3.85 TB/s
// shared L2-write wall ~= 8.7us + ~2us graph gap). One CTA per (batch,
// 64-timestep chunk), 512 CTAs. Keras masked-LSTM semantics: state updates
// ONLY where token == 0 (mask True); elsewhere h/c carry and out[b,t] is the
// carried h1. So a chunk with no zero token at any t < t_end outputs exactly
// the zero vector -> prologue = one int4 load + one barrier-or, then pure
// streaming .cs stores. Rare case: CTA replays the masked LSTM up to its
// chunk end (exact for arbitrary inputs; siblings duplicate deterministically).
__global__ __launch_bounds__(256)
void lstm_fused_kernel(const int*   __restrict__ x,
                       const float* __restrict__ emb,
                       const float* __restrict__ k0,
                       const float* __restrict__ r0,
                       const float* __restrict__ b0,
                       const float* __restrict__ k1,
                       const float* __restrict__ r1,
                       const float* __restrict__ b1,
                       float*       __restrict__ out)
{
    const int b     = blockIdx.x >> 3;
    const int chunk = blockIdx.x & (NCHUNK - 1);
    const int t0    = chunk * CHUNK;
    const int t_end = t0 + CHUNK;
    const int j     = threadIdx.x;            // 0..255

    // ---- any zero token in [0, t_end)?  one int4 load + one barrier-or ----
    const int n4 = t_end >> 2;                 // 16..128 int4 words
    int pred = 0;
    if (j < n4) {
        const int4 v = reinterpret_cast<const int4*>(x + (size_t)b * T)[j];
        pred = (v.x == 0) | (v.y == 0) | (v.z == 0) | (v.w == 0);
    }
    const int any = __syncthreads_or(pred);

    if (!any) {
        // -------- common fast path: chunk output is exactly zero --------
        const float4 zv = make_float4(0.f, 0.f, 0.f, 0.f);
        float4* dst = reinterpret_cast<float4*>(out + (size_t)b * T * U + (size_t)t0 * U)
                      + j;
        #pragma unroll
        for (int i = 0; i < 16; i++)           // 64*256 floats = 4096 f4 / 256 thr
            __stcs(dst + i * 256, zv);
        if (chunk == NCHUNK - 1) {             // whole row inactive -> final h == 0
            float4* hdst = reinterpret_cast<float4*>(out + (size_t)B * T * U + (size_t)b * U);
            if (j < U / 4) __stcs(hdst + j, zv);
        }
        return;
    }

    // -------- rare general path: replay the masked LSTM up to t_end --------
    __shared__ int   acts[T];
    __shared__ float h0s[U];
    __shared__ float h1s[U];
    __shared__ float zbuf[Z];
    __shared__ float embs[E];

    for (int t = j; t < t_end; t += 256)
        acts[t] = (x[(size_t)b * T + t] == 0);

    embs[j] = emb[j];            // embedding row of token 0
    h0s[j]  = 0.0f;
    h1s[j]  = 0.0f;
    __syncthreads();

    // Constant layer-0 x-contribution: xz = emb[0,:] @ k0 + b0.
    // Thread j owns gate columns 4j..4j+3 (float4 across Z).
    float4 xz = reinterpret_cast<const float4*>(b0)[j];
    for (int e = 0; e < E; e++) {
        const float  ev = embs[e];
        const float4 kv = reinterpret_cast<const float4*>(k0 + (size_t)e * Z)[j];
        xz.x += ev * kv.x; xz.y += ev * kv.y; xz.z += ev * kv.z; xz.w += ev * kv.w;
    }
    const float4 b1v = reinterpret_cast<const float4*>(b1)[j];

    float c0 = 0.0f, c1 = 0.0f;

    for (int t = 0; t < t_end; t++) {
        if (acts[t]) {
            // ---- layer 0: z = xz + h0 @ r0 ----
            float4 z = xz;
            #pragma unroll 4
            for (int k = 0; k < U; k++) {
                const float  hv = h0s[k];
                const float4 rv = reinterpret_cast<const float4*>(r0 + (size_t)k * Z)[j];
                z.x += hv * rv.x; z.y += hv * rv.y; z.z += hv * rv.z; z.w += hv * rv.w;
            }
            reinterpret_cast<float4*>(zbuf)[j] = z;
            __syncthreads();
            {
                const float ig = sigm (zbuf[0 * U + j]);
                const float fg = sigm (zbuf[1 * U + j]);
                const float gg = tanhf(zbuf[2 * U + j]);
                const float og = sigm (zbuf[3 * U + j]);
                c0 = fg * c0 + ig * gg;
                __syncthreads();               // matvec reads of h0s fully done
                h0s[j] = og * tanhf(c0);
            }
            __syncthreads();

            // ---- layer 1: w = b1 + h0 @ k1 + h1 @ r1 ----
            float4 w = b1v;
            #pragma unroll 2
            for (int k = 0; k < U; k++) {
                const float  h0v = h0s[k];
                const float  h1v = h1s[k];
                const float4 kv = reinterpret_cast<const float4*>(k1 + (size_t)k * Z)[j];
                const float4 rv = reinterpret_cast<const float4*>(r1 + (size_t)k * Z)[j];
                w.x += h0v * kv.x + h1v * rv.x;
                w.y += h0v * kv.y + h1v * rv.y;
                w.z += h0v * kv.z + h1v * rv.z;
                w.w += h0v * kv.w + h1v * rv.w;
            }
            __syncthreads();                   // prior zbuf reads done
            reinterpret_cast<float4*>(zbuf)[j] = w;
            __syncthreads();
            {
                const float ig = sigm (zbuf[0 * U + j]);
                const float fg = sigm (zbuf[1 * U + j]);
                const float gg = tanhf(zbuf[2 * U + j]);
                const float og = sigm (zbuf[3 * U + j]);
                c1 = fg * c1 + ig * gg;
                __syncthreads();               // matvec reads of h1s fully done
                h1s[j] = og * tanhf(c1);
            }
            __syncthreads();
        }
        if (t >= t0)
            out[(size_t)b * T * U + (size_t)t * U + j] = h1s[j];
    }

    if (chunk == NCHUNK - 1)                   // ran the full sequence
        out[(size_t)B * T * U + (size_t)b * U + j] = h1s[j];
}

extern "C" void kernel_launch(void* const* d_in, const int* in_sizes, int n_in,
                              void* d_out, int out_size)
{
    const int*   x   = (const int*)  d_in[0];
    const float* emb = (const float*)d_in[1];
    const float* k0  = (const float*)d_in[2];
    const float* r0  = (const float*)d_in[3];
    const float* b0  = (const float*)d_in[4];
    const float* k1  = (const float*)d_in[5];
    const float* r1  = (const float*)d_in[6];
    const float* b1  = (const float*)d_in[7];
    float* out = (float*)d_out;

    lstm_fused_kernel<<<B * NCHUNK, 256>>>(x, emb, k0, r0, b0, k1, r1, b1, out);
}